// round 11
// baseline (speedup 1.0000x reference)
#include <cuda_runtime.h>
#include <cuda_fp16.h>
#include <cstdint>

#define NUM_DST   10000
#define NUM_EDGES 600000
#define DN   100
#define DE   172
#define DTF  100
#define DOUT 128
#define KDIM (DN + DE + DTF)   // 372
#define NPC  6                 // k-pair chunks: k = it*64 + lane*2

// ---------------- scratch ----------------------------------------------------
__device__ float   g_qnodes[NUM_DST * DOUT];
__device__ float   g_qbk[NUM_DST * 2];
__device__ __half2 g_Pqh[(size_t)NUM_DST * KDIM];   // [d][k] -> (head0, head1) fp16
__device__ float2  g_U[(size_t)NUM_DST * KDIM];     // [d][k] -> (head0, head1) fp32
__device__ float   g_z[NUM_DST * 2];
__device__ float   g_qbias[DOUT];
__device__ float   g_absum[2];

#define U_FLOAT4 ((NUM_DST * KDIM * 2) / 4)   // 1,860,000
#define Z_FLOAT4 ((NUM_DST * 2) / 4)          // 5,000

// ---------------- kernel 0: init (vectorized zero) + derived constants -------
__global__ void init_kernel(const float* __restrict__ time_b,
                            const float* __restrict__ wq,
                            const float* __restrict__ bq,
                            const float* __restrict__ att_bias)
{
    int idx = blockIdx.x * blockDim.x + threadIdx.x;
    float4 zero4 = make_float4(0.f, 0.f, 0.f, 0.f);
    if (idx < U_FLOAT4) ((float4*)g_U)[idx] = zero4;
    if (idx < Z_FLOAT4) ((float4*)g_z)[idx] = zero4;
    if (idx < DOUT) {
        float acc = bq[idx];
        #pragma unroll 4
        for (int t = 0; t < DTF; t++)
            acc += cosf(time_b[t]) * wq[(DN + t) * DOUT + idx];
        g_qbias[idx] = acc;
    }
    if (idx < 2) {
        float s = 0.f;
        for (int j = 0; j < DOUT / 2; j++) s += att_bias[idx * (DOUT / 2) + j];
        g_absum[idx] = s;
    }
}

// ---------------- kernel 1: Q per dst node (8 dst / block) + Q.bk ------------
__global__ __launch_bounds__(128) void qnode_kernel(const float* __restrict__ h,
                                                    const float* __restrict__ wq,
                                                    const float* __restrict__ bk)
{
    int dbase = blockIdx.x * 8;
    int c = threadIdx.x;
    __shared__ float sh[8][DN];
    __shared__ float part[8][4];
    for (int i = c; i < 8 * DN; i += 128) {
        int dl = i / DN, k = i - dl * DN;
        sh[dl][k] = h[(size_t)(dbase + dl) * DN + k];
    }
    __syncthreads();
    float qb = g_qbias[c];
    float a[8];
    #pragma unroll
    for (int d = 0; d < 8; d++) a[d] = qb;
    #pragma unroll 4
    for (int k = 0; k < DN; k++) {
        float w = wq[k * DOUT + c];
        #pragma unroll
        for (int d = 0; d < 8; d++) a[d] = fmaf(sh[d][k], w, a[d]);
    }
    #pragma unroll
    for (int d = 0; d < 8; d++)
        g_qnodes[(dbase + d) * DOUT + c] = a[d];

    // qbk[d][h] = sum_c q[d][c] * bk[c]  (head h = cols 64h..64h+63)
    float bkc = bk[c];
    float p[8];
    #pragma unroll
    for (int d = 0; d < 8; d++) p[d] = a[d] * bkc;
    #pragma unroll
    for (int off = 16; off > 0; off >>= 1)
        #pragma unroll
        for (int d = 0; d < 8; d++)
            p[d] += __shfl_xor_sync(0xffffffffu, p[d], off);
    int warp = c >> 5;
    if ((c & 31) == 0)
        #pragma unroll
        for (int d = 0; d < 8; d++) part[d][warp] = p[d];
    __syncthreads();
    if (c < 16) {
        int d = c >> 1, hh = c & 1;
        g_qbk[(dbase + d) * 2 + hh] = part[d][hh * 2] + part[d][hh * 2 + 1];
    }
}

// ---------------- kernel 1b: Pq[d,k,h] = sum_c qn[d,64h+c] * wk[k,64h+c] -----
__global__ __launch_bounds__(256) void pq_kernel(const float* __restrict__ wk)
{
    __shared__ float qs[64][129];
    __shared__ float ws[64][129];
    int dbase = blockIdx.x * 64;
    int kbase = blockIdx.y * 64;
    int tid = threadIdx.x;
    for (int i = tid; i < 64 * 128; i += 256) {
        int r = i >> 7, c = i & 127;
        int d = dbase + r;
        qs[r][c] = (d < NUM_DST) ? g_qnodes[d * DOUT + c] : 0.f;
        int k = kbase + r;
        ws[r][c] = (k < KDIM) ? wk[k * DOUT + c] : 0.f;
    }
    __syncthreads();
    int tx = tid & 15, ty = tid >> 4;
    float acc[2][4][4];
    #pragma unroll
    for (int hh = 0; hh < 2; hh++)
        #pragma unroll
        for (int i = 0; i < 4; i++)
            #pragma unroll
            for (int j = 0; j < 4; j++) acc[hh][i][j] = 0.f;

    #pragma unroll 1
    for (int hh = 0; hh < 2; hh++) {
        for (int c = 0; c < 64; c++) {
            float q[4], w[4];
            #pragma unroll
            for (int i = 0; i < 4; i++) q[i] = qs[ty * 4 + i][hh * 64 + c];
            #pragma unroll
            for (int j = 0; j < 4; j++) w[j] = ws[tx * 4 + j][hh * 64 + c];
            #pragma unroll
            for (int i = 0; i < 4; i++)
                #pragma unroll
                for (int j = 0; j < 4; j++)
                    acc[hh][i][j] = fmaf(q[i], w[j], acc[hh][i][j]);
        }
    }
    #pragma unroll
    for (int i = 0; i < 4; i++) {
        int d = dbase + ty * 4 + i;
        if (d >= NUM_DST) continue;
        #pragma unroll
        for (int j = 0; j < 4; j++) {
            int k = kbase + tx * 4 + j;
            if (k >= KDIM) continue;
            g_Pqh[(size_t)d * KDIM + k] =
                __floats2half2_rn(acc[0][i][j], acc[1][i][j]);
        }
    }
}

// ---------------- kernel 2: per-edge warp, k-pair mapping (UNCHANGED R10) ----
__global__ __launch_bounds__(256) void scoreU_kernel(
    const float* __restrict__ h,   const float* __restrict__ ef,
    const float* __restrict__ dt,  const int*   __restrict__ dst_idx,
    const float* __restrict__ time_w, const float* __restrict__ time_b)
{
    int e = (blockIdx.x * 256 + threadIdx.x) >> 5;
    if (e >= NUM_EDGES) return;
    int lane = threadIdx.x & 31;
    float td = dt[e];
    int d = dst_idx[e];
    const float* __restrict__ hrow  = h + (size_t)(NUM_DST + e) * DN;
    const float* __restrict__ efrow = ef + (size_t)e * DE;

    float2 v[NPC];
    #pragma unroll
    for (int it = 0; it < NPC; it++) {
        int k = it * 64 + lane * 2;
        float2 t = make_float2(0.f, 0.f);
        if (k < DN) {
            t = __ldg((const float2*)(hrow + k));
        } else if (k < DN + DE) {
            t = __ldg((const float2*)(efrow + (k - DN)));
        } else if (k < KDIM) {
            int t0 = k - DN - DE;
            t.x = __cosf(td * time_w[t0]     + time_b[t0]);
            t.y = __cosf(td * time_w[t0 + 1] + time_b[t0 + 1]);
        }
        v[it] = t;
    }
    const __half2* __restrict__ pq = g_Pqh + (size_t)d * KDIM;
    float2 p[NPC][2];
    #pragma unroll
    for (int it = 0; it < NPC; it++) {
        int k = it * 64 + lane * 2;
        if (k < KDIM) {
            uint2 raw = __ldg((const uint2*)(pq + k));
            p[it][0] = __half22float2(*(__half2*)&raw.x);
            p[it][1] = __half22float2(*(__half2*)&raw.y);
        } else {
            p[it][0] = make_float2(0.f, 0.f);
            p[it][1] = make_float2(0.f, 0.f);
        }
    }
    float a0 = 0.f, a1 = 0.f;
    #pragma unroll
    for (int it = 0; it < NPC; it++) {
        a0 = fmaf(v[it].x, p[it][0].x, a0);
        a1 = fmaf(v[it].x, p[it][0].y, a1);
        a0 = fmaf(v[it].y, p[it][1].x, a0);
        a1 = fmaf(v[it].y, p[it][1].y, a1);
    }
    #pragma unroll
    for (int off = 16; off > 0; off >>= 1) {
        a0 += __shfl_xor_sync(0xffffffffu, a0, off);
        a1 += __shfl_xor_sync(0xffffffffu, a1, off);
    }
    float s0 = a0 + g_absum[0] + g_qbk[d * 2 + 0];
    float s1 = a1 + g_absum[1] + g_qbk[d * 2 + 1];
    s0 = s0 > 0.f ? s0 : 0.2f * s0;
    s1 = s1 > 0.f ? s1 : 0.2f * s1;
    float e0 = __expf(fminf(s0, 80.f));
    float e1 = __expf(fminf(s1, 80.f));
    if (lane == 0) {
        atomicAdd(&g_z[d * 2 + 0], e0);
        atomicAdd(&g_z[d * 2 + 1], e1);
    }
    float2* __restrict__ Urow = g_U + (size_t)d * KDIM;
    #pragma unroll
    for (int it = 0; it < NPC; it++) {
        int k = it * 64 + lane * 2;
        if (k < KDIM) {
            float x0 = v[it].x * e0;
            float y0 = v[it].x * e1;
            float x1 = v[it].y * e0;
            float y1 = v[it].y * e1;
            asm volatile("red.global.add.v4.f32 [%0], {%1,%2,%3,%4};"
                         :: "l"(Urow + k), "f"(x0), "f"(y0), "f"(x1), "f"(y1)
                         : "memory");
        }
    }
}

// ---------------- kernel 3: fused agg+out+LN, 16 dst / 256-thread block ------
// thread t: column c = t & 127, dst-half g = t >> 7 (8 dsts each).
__global__ __launch_bounds__(256) void outfused_kernel(
    const float* __restrict__ h,    const float* __restrict__ wv,
    const float* __restrict__ bv,   const float* __restrict__ wout,
    const float* __restrict__ bout, const float* __restrict__ ln_g,
    const float* __restrict__ ln_b, float* __restrict__ out)
{
    int dbase = blockIdx.x * 16;
    int t = threadIdx.x;
    int c = t & 127;
    int g = t >> 7;            // 0 or 1
    int hh = c >> 6;
    __shared__ float sU[16][KDIM * 2];
    __shared__ float sZ[16][2];
    __shared__ float sin[16][DOUT + DN];
    __shared__ float red1[16][4], red2[16][4];

    if (t < 32) {
        int d = t >> 1, j = t & 1;
        sZ[d][j] = g_z[(dbase + d) * 2 + j];
    }
    __syncthreads();
    for (int i = t; i < 16 * KDIM * 2; i += 256) {
        int d = i / (KDIM * 2);
        int j = i - d * (KDIM * 2);
        float z = sZ[d][j & 1];
        float u = ((const float*)(g_U + (size_t)(dbase + d) * KDIM))[j];
        sU[d][j] = (z > 0.f) ? (u / z) : 0.f;
    }
    for (int i = t; i < 16 * DN; i += 256) {
        int d = i / DN, k = i - d * DN;
        sin[d][DOUT + k] = h[(size_t)(dbase + d) * DN + k];
    }
    __syncthreads();

    // agg column c for this thread's 8 dsts
    float acc[8];
    #pragma unroll
    for (int d = 0; d < 8; d++) acc[d] = 0.f;
    #pragma unroll 4
    for (int k = 0; k < KDIM; k++) {
        float w = wv[k * DOUT + c];
        #pragma unroll
        for (int d = 0; d < 8; d++)
            acc[d] = fmaf(sU[g * 8 + d][k * 2 + hh], w, acc[d]);
    }
    float bvc = bv[c];
    #pragma unroll
    for (int d = 0; d < 8; d++)
        sin[g * 8 + d][c] = (sZ[g * 8 + d][hh] > 0.f) ? (acc[d] + bvc) : 0.f;
    __syncthreads();

    // out GEMM over concat(agg, h)
    float b0 = bout[c];
    float a[8];
    #pragma unroll
    for (int d = 0; d < 8; d++) a[d] = b0;
    #pragma unroll 4
    for (int k = 0; k < DOUT + DN; k++) {
        float w = wout[k * DOUT + c];
        #pragma unroll
        for (int d = 0; d < 8; d++) a[d] = fmaf(sin[g * 8 + d][k], w, a[d]);
    }
    float s1[8], s2[8];
    #pragma unroll
    for (int d = 0; d < 8; d++) {
        a[d] = fmaxf(a[d], 0.f);
        s1[d] = a[d];
        s2[d] = a[d] * a[d];
    }
    #pragma unroll
    for (int off = 16; off > 0; off >>= 1) {
        #pragma unroll
        for (int d = 0; d < 8; d++) {
            s1[d] += __shfl_xor_sync(0xffffffffu, s1[d], off);
            s2[d] += __shfl_xor_sync(0xffffffffu, s2[d], off);
        }
    }
    int warp = (t >> 5) & 3;   // warp index within the dst-half (c covers 128)
    if ((t & 31) == 0) {
        #pragma unroll
        for (int d = 0; d < 8; d++) {
            red1[g * 8 + d][warp] = s1[d];
            red2[g * 8 + d][warp] = s2[d];
        }
    }
    __syncthreads();
    #pragma unroll
    for (int d = 0; d < 8; d++) {
        int dd = g * 8 + d;
        float t1 = red1[dd][0] + red1[dd][1] + red1[dd][2] + red1[dd][3];
        float t2 = red2[dd][0] + red2[dd][1] + red2[dd][2] + red2[dd][3];
        float mu  = t1 * (1.f / DOUT);
        float var = t2 * (1.f / DOUT) - mu * mu;
        out[(size_t)(dbase + dd) * DOUT + c] =
            (a[d] - mu) * rsqrtf(var + 1e-5f) * ln_g[c] + ln_b[c];
    }
}

// ---------------- launch -----------------------------------------------------
extern "C" void kernel_launch(void* const* d_in, const int* in_sizes, int n_in,
                              void* d_out, int out_size)
{
    int off = (n_in >= 18 && in_sizes[4] == 1) ? 1 : 0;
    const float* h        = (const float*)d_in[0];
    const float* ef       = (const float*)d_in[1];
    const float* dt       = (const float*)d_in[2];
    const int*   dst_idx  = (const int*)  d_in[3];
    const float* time_w   = (const float*)d_in[4 + off];
    const float* time_b   = (const float*)d_in[5 + off];
    const float* wq       = (const float*)d_in[6 + off];
    const float* bq       = (const float*)d_in[7 + off];
    const float* wk       = (const float*)d_in[8 + off];
    const float* bk       = (const float*)d_in[9 + off];
    const float* wv       = (const float*)d_in[10 + off];
    const float* bv       = (const float*)d_in[11 + off];
    const float* att_bias = (const float*)d_in[12 + off];
    const float* wout     = (const float*)d_in[13 + off];
    const float* bout     = (const float*)d_in[14 + off];
    const float* ln_g     = (const float*)d_in[15 + off];
    const float* ln_b     = (const float*)d_in[16 + off];
    float* out = (float*)d_out;

    init_kernel<<<(U_FLOAT4 + 255) / 256, 256>>>(time_b, wq, bq, att_bias);
    qnode_kernel<<<NUM_DST / 8, 128>>>(h, wq, bk);
    pq_kernel<<<dim3((NUM_DST + 63) / 64, (KDIM + 63) / 64), 256>>>(wk);
    scoreU_kernel<<<NUM_EDGES / 8, 256>>>(h, ef, dt, dst_idx, time_w, time_b);
    outfused_kernel<<<NUM_DST / 16, 256>>>(h, wv, bv, wout, bout, ln_g, ln_b, out);
}

// round 12
// speedup vs baseline: 1.0131x; 1.0131x over previous
#include <cuda_runtime.h>
#include <cuda_fp16.h>
#include <cstdint>

#define NUM_DST   10000
#define NUM_EDGES 600000
#define DN   100
#define DE   172
#define DTF  100
#define DOUT 128
#define KDIM (DN + DE + DTF)   // 372
#define NPC  6                 // k-pair chunks: k = it*64 + lane*2

// ---------------- scratch ----------------------------------------------------
__device__ float   g_qnodes[NUM_DST * DOUT];
__device__ float   g_qbk[NUM_DST * 2];
__device__ __half2 g_Pqh[(size_t)NUM_DST * KDIM];   // [d][k] -> (head0, head1) fp16
__device__ float2  g_U[(size_t)NUM_DST * KDIM];     // [d][k] -> (head0, head1) fp32
__device__ float   g_z[NUM_DST * 2];
__device__ float   g_qbias[DOUT];
__device__ float   g_absum[2];

#define U_FLOAT4 ((NUM_DST * KDIM * 2) / 4)   // 1,860,000
#define Z_FLOAT4 ((NUM_DST * 2) / 4)          // 5,000

// ---------------- kernel 0: init (vectorized zero) + derived constants -------
__global__ void init_kernel(const float* __restrict__ time_b,
                            const float* __restrict__ wq,
                            const float* __restrict__ bq,
                            const float* __restrict__ att_bias)
{
    int idx = blockIdx.x * blockDim.x + threadIdx.x;
    float4 zero4 = make_float4(0.f, 0.f, 0.f, 0.f);
    if (idx < U_FLOAT4) ((float4*)g_U)[idx] = zero4;
    if (idx < Z_FLOAT4) ((float4*)g_z)[idx] = zero4;
    if (idx < DOUT) {
        float acc = bq[idx];
        #pragma unroll 4
        for (int t = 0; t < DTF; t++)
            acc += cosf(time_b[t]) * wq[(DN + t) * DOUT + idx];
        g_qbias[idx] = acc;
    }
    if (idx < 2) {
        float s = 0.f;
        for (int j = 0; j < DOUT / 2; j++) s += att_bias[idx * (DOUT / 2) + j];
        g_absum[idx] = s;
    }
}

// ---------------- kernel 1: Q per dst node (8 dst / block) + Q.bk ------------
__global__ __launch_bounds__(128) void qnode_kernel(const float* __restrict__ h,
                                                    const float* __restrict__ wq,
                                                    const float* __restrict__ bk)
{
    int dbase = blockIdx.x * 8;
    int c = threadIdx.x;
    __shared__ float sh[8][DN];
    __shared__ float part[8][4];
    for (int i = c; i < 8 * DN; i += 128) {
        int dl = i / DN, k = i - dl * DN;
        sh[dl][k] = h[(size_t)(dbase + dl) * DN + k];
    }
    __syncthreads();
    float qb = g_qbias[c];
    float a[8];
    #pragma unroll
    for (int d = 0; d < 8; d++) a[d] = qb;
    #pragma unroll 4
    for (int k = 0; k < DN; k++) {
        float w = wq[k * DOUT + c];
        #pragma unroll
        for (int d = 0; d < 8; d++) a[d] = fmaf(sh[d][k], w, a[d]);
    }
    #pragma unroll
    for (int d = 0; d < 8; d++)
        g_qnodes[(dbase + d) * DOUT + c] = a[d];

    float bkc = bk[c];
    float p[8];
    #pragma unroll
    for (int d = 0; d < 8; d++) p[d] = a[d] * bkc;
    #pragma unroll
    for (int off = 16; off > 0; off >>= 1)
        #pragma unroll
        for (int d = 0; d < 8; d++)
            p[d] += __shfl_xor_sync(0xffffffffu, p[d], off);
    int warp = c >> 5;
    if ((c & 31) == 0)
        #pragma unroll
        for (int d = 0; d < 8; d++) part[d][warp] = p[d];
    __syncthreads();
    if (c < 16) {
        int d = c >> 1, hh = c & 1;
        g_qbk[(dbase + d) * 2 + hh] = part[d][hh * 2] + part[d][hh * 2 + 1];
    }
}

// ---------------- kernel 1b: Pq[d,k,h] = sum_c qn[d,64h+c] * wk[k,64h+c] -----
__global__ __launch_bounds__(256) void pq_kernel(const float* __restrict__ wk)
{
    __shared__ float qs[64][129];
    __shared__ float ws[64][129];
    int dbase = blockIdx.x * 64;
    int kbase = blockIdx.y * 64;
    int tid = threadIdx.x;
    for (int i = tid; i < 64 * 128; i += 256) {
        int r = i >> 7, c = i & 127;
        int d = dbase + r;
        qs[r][c] = (d < NUM_DST) ? g_qnodes[d * DOUT + c] : 0.f;
        int k = kbase + r;
        ws[r][c] = (k < KDIM) ? wk[k * DOUT + c] : 0.f;
    }
    __syncthreads();
    int tx = tid & 15, ty = tid >> 4;
    float acc[2][4][4];
    #pragma unroll
    for (int hh = 0; hh < 2; hh++)
        #pragma unroll
        for (int i = 0; i < 4; i++)
            #pragma unroll
            for (int j = 0; j < 4; j++) acc[hh][i][j] = 0.f;

    #pragma unroll 1
    for (int hh = 0; hh < 2; hh++) {
        for (int c = 0; c < 64; c++) {
            float q[4], w[4];
            #pragma unroll
            for (int i = 0; i < 4; i++) q[i] = qs[ty * 4 + i][hh * 64 + c];
            #pragma unroll
            for (int j = 0; j < 4; j++) w[j] = ws[tx * 4 + j][hh * 64 + c];
            #pragma unroll
            for (int i = 0; i < 4; i++)
                #pragma unroll
                for (int j = 0; j < 4; j++)
                    acc[hh][i][j] = fmaf(q[i], w[j], acc[hh][i][j]);
        }
    }
    #pragma unroll
    for (int i = 0; i < 4; i++) {
        int d = dbase + ty * 4 + i;
        if (d >= NUM_DST) continue;
        #pragma unroll
        for (int j = 0; j < 4; j++) {
            int k = kbase + tx * 4 + j;
            if (k >= KDIM) continue;
            g_Pqh[(size_t)d * KDIM + k] =
                __floats2half2_rn(acc[0][i][j], acc[1][i][j]);
        }
    }
}

// ---------------- kernel 2: per-edge warp, k-pair mapping, static guards -----
// lane L owns k = it*64 + 2L. Chunks 0..4 are fully in-range (k<=318<372) ->
// no guards. Chunk 5 guarded (k in [320,382]). kv via __ldcs (evict-first:
// read-once stream, protects Pq/U L2 residency).
__global__ __launch_bounds__(256) void scoreU_kernel(
    const float* __restrict__ h,   const float* __restrict__ ef,
    const float* __restrict__ dt,  const int*   __restrict__ dst_idx,
    const float* __restrict__ time_w, const float* __restrict__ time_b)
{
    int e = (blockIdx.x * 256 + threadIdx.x) >> 5;
    if (e >= NUM_EDGES) return;
    int lane = threadIdx.x & 31;
    float td = dt[e];
    int d = dst_idx[e];
    const float* __restrict__ hrow  = h + (size_t)(NUM_DST + e) * DN;
    const float* __restrict__ efrow = ef + (size_t)e * DE;
    const int k2 = lane * 2;

    // kv pairs: chunks 0..4 unguarded, chunk 5 guarded
    float2 v[NPC];
    #pragma unroll
    for (int it = 0; it < 5; it++) {
        int k = it * 64 + k2;
        float2 t;
        if (k < DN) {
            t = __ldcs((const float2*)(hrow + k));
        } else if (k < DN + DE) {
            t = __ldcs((const float2*)(efrow + (k - DN)));
        } else {
            int t0 = k - DN - DE;
            t.x = __cosf(td * time_w[t0]     + time_b[t0]);
            t.y = __cosf(td * time_w[t0 + 1] + time_b[t0 + 1]);
        }
        v[it] = t;
    }
    {
        int k = 5 * 64 + k2;           // [320, 382] — all in time segment
        float2 t = make_float2(0.f, 0.f);
        if (k < KDIM) {
            int t0 = k - DN - DE;
            t.x = __cosf(td * time_w[t0]     + time_b[t0]);
            t.y = __cosf(td * time_w[t0 + 1] + time_b[t0 + 1]);
        }
        v[5] = t;
    }

    // Pq pairs: chunks 0..4 unguarded, chunk 5 guarded
    const __half2* __restrict__ pq = g_Pqh + (size_t)d * KDIM;
    float2 p[NPC][2];
    #pragma unroll
    for (int it = 0; it < 5; it++) {
        uint2 raw = __ldg((const uint2*)(pq + it * 64 + k2));
        p[it][0] = __half22float2(*(__half2*)&raw.x);
        p[it][1] = __half22float2(*(__half2*)&raw.y);
    }
    if (5 * 64 + k2 < KDIM) {
        uint2 raw = __ldg((const uint2*)(pq + 5 * 64 + k2));
        p[5][0] = __half22float2(*(__half2*)&raw.x);
        p[5][1] = __half22float2(*(__half2*)&raw.y);
    } else {
        p[5][0] = make_float2(0.f, 0.f);
        p[5][1] = make_float2(0.f, 0.f);
    }

    float a0 = 0.f, a1 = 0.f;
    #pragma unroll
    for (int it = 0; it < NPC; it++) {
        a0 = fmaf(v[it].x, p[it][0].x, a0);
        a1 = fmaf(v[it].x, p[it][0].y, a1);
        a0 = fmaf(v[it].y, p[it][1].x, a0);
        a1 = fmaf(v[it].y, p[it][1].y, a1);
    }
    #pragma unroll
    for (int off = 16; off > 0; off >>= 1) {
        a0 += __shfl_xor_sync(0xffffffffu, a0, off);
        a1 += __shfl_xor_sync(0xffffffffu, a1, off);
    }
    float2 qbk = *(const float2*)(g_qbk + d * 2);
    float s0 = a0 + g_absum[0] + qbk.x;
    float s1 = a1 + g_absum[1] + qbk.y;
    s0 = s0 > 0.f ? s0 : 0.2f * s0;
    s1 = s1 > 0.f ? s1 : 0.2f * s1;
    float e0 = __expf(fminf(s0, 80.f));
    float e1 = __expf(fminf(s1, 80.f));
    if (lane == 0) {
        asm volatile("red.global.add.v2.f32 [%0], {%1,%2};"
                     :: "l"(g_z + d * 2), "f"(e0), "f"(e1) : "memory");
    }
    // U: one red.v4 per pair — chunks 0..4 unguarded, chunk 5 guarded
    float2* __restrict__ Urow = g_U + (size_t)d * KDIM;
    #pragma unroll
    for (int it = 0; it < 5; it++) {
        int k = it * 64 + k2;
        float x0 = v[it].x * e0;
        float y0 = v[it].x * e1;
        float x1 = v[it].y * e0;
        float y1 = v[it].y * e1;
        asm volatile("red.global.add.v4.f32 [%0], {%1,%2,%3,%4};"
                     :: "l"(Urow + k), "f"(x0), "f"(y0), "f"(x1), "f"(y1)
                     : "memory");
    }
    if (5 * 64 + k2 < KDIM) {
        float x0 = v[5].x * e0;
        float y0 = v[5].x * e1;
        float x1 = v[5].y * e0;
        float y1 = v[5].y * e1;
        asm volatile("red.global.add.v4.f32 [%0], {%1,%2,%3,%4};"
                     :: "l"(Urow + 5 * 64 + k2), "f"(x0), "f"(y0), "f"(x1), "f"(y1)
                     : "memory");
    }
}

// ---------------- kernel 3: fused agg+out+LN, 16 dst / 256-thread block ------
__global__ __launch_bounds__(256) void outfused_kernel(
    const float* __restrict__ h,    const float* __restrict__ wv,
    const float* __restrict__ bv,   const float* __restrict__ wout,
    const float* __restrict__ bout, const float* __restrict__ ln_g,
    const float* __restrict__ ln_b, float* __restrict__ out)
{
    int dbase = blockIdx.x * 16;
    int t = threadIdx.x;
    int c = t & 127;
    int g = t >> 7;
    int hh = c >> 6;
    __shared__ float sU[16][KDIM * 2];
    __shared__ float sZ[16][2];
    __shared__ float sin[16][DOUT + DN];
    __shared__ float red1[16][4], red2[16][4];

    if (t < 32) {
        int d = t >> 1, j = t & 1;
        sZ[d][j] = g_z[(dbase + d) * 2 + j];
    }
    __syncthreads();
    for (int i = t; i < 16 * KDIM * 2; i += 256) {
        int d = i / (KDIM * 2);
        int j = i - d * (KDIM * 2);
        float z = sZ[d][j & 1];
        float u = ((const float*)(g_U + (size_t)(dbase + d) * KDIM))[j];
        sU[d][j] = (z > 0.f) ? (u / z) : 0.f;
    }
    for (int i = t; i < 16 * DN; i += 256) {
        int d = i / DN, k = i - d * DN;
        sin[d][DOUT + k] = h[(size_t)(dbase + d) * DN + k];
    }
    __syncthreads();

    float acc[8];
    #pragma unroll
    for (int d = 0; d < 8; d++) acc[d] = 0.f;
    #pragma unroll 4
    for (int k = 0; k < KDIM; k++) {
        float w = wv[k * DOUT + c];
        #pragma unroll
        for (int d = 0; d < 8; d++)
            acc[d] = fmaf(sU[g * 8 + d][k * 2 + hh], w, acc[d]);
    }
    float bvc = bv[c];
    #pragma unroll
    for (int d = 0; d < 8; d++)
        sin[g * 8 + d][c] = (sZ[g * 8 + d][hh] > 0.f) ? (acc[d] + bvc) : 0.f;
    __syncthreads();

    float b0 = bout[c];
    float a[8];
    #pragma unroll
    for (int d = 0; d < 8; d++) a[d] = b0;
    #pragma unroll 4
    for (int k = 0; k < DOUT + DN; k++) {
        float w = wout[k * DOUT + c];
        #pragma unroll
        for (int d = 0; d < 8; d++) a[d] = fmaf(sin[g * 8 + d][k], w, a[d]);
    }
    float s1[8], s2[8];
    #pragma unroll
    for (int d = 0; d < 8; d++) {
        a[d] = fmaxf(a[d], 0.f);
        s1[d] = a[d];
        s2[d] = a[d] * a[d];
    }
    #pragma unroll
    for (int off = 16; off > 0; off >>= 1) {
        #pragma unroll
        for (int d = 0; d < 8; d++) {
            s1[d] += __shfl_xor_sync(0xffffffffu, s1[d], off);
            s2[d] += __shfl_xor_sync(0xffffffffu, s2[d], off);
        }
    }
    int warp = (t >> 5) & 3;
    if ((t & 31) == 0) {
        #pragma unroll
        for (int d = 0; d < 8; d++) {
            red1[g * 8 + d][warp] = s1[d];
            red2[g * 8 + d][warp] = s2[d];
        }
    }
    __syncthreads();
    #pragma unroll
    for (int d = 0; d < 8; d++) {
        int dd = g * 8 + d;
        float t1 = red1[dd][0] + red1[dd][1] + red1[dd][2] + red1[dd][3];
        float t2 = red2[dd][0] + red2[dd][1] + red2[dd][2] + red2[dd][3];
        float mu  = t1 * (1.f / DOUT);
        float var = t2 * (1.f / DOUT) - mu * mu;
        out[(size_t)(dbase + dd) * DOUT + c] =
            (a[d] - mu) * rsqrtf(var + 1e-5f) * ln_g[c] + ln_b[c];
    }
}

// ---------------- launch -----------------------------------------------------
extern "C" void kernel_launch(void* const* d_in, const int* in_sizes, int n_in,
                              void* d_out, int out_size)
{
    int off = (n_in >= 18 && in_sizes[4] == 1) ? 1 : 0;
    const float* h        = (const float*)d_in[0];
    const float* ef       = (const float*)d_in[1];
    const float* dt       = (const float*)d_in[2];
    const int*   dst_idx  = (const int*)  d_in[3];
    const float* time_w   = (const float*)d_in[4 + off];
    const float* time_b   = (const float*)d_in[5 + off];
    const float* wq       = (const float*)d_in[6 + off];
    const float* bq       = (const float*)d_in[7 + off];
    const float* wk       = (const float*)d_in[8 + off];
    const float* bk       = (const float*)d_in[9 + off];
    const float* wv       = (const float*)d_in[10 + off];
    const float* bv       = (const float*)d_in[11 + off];
    const float* att_bias = (const float*)d_in[12 + off];
    const float* wout     = (const float*)d_in[13 + off];
    const float* bout     = (const float*)d_in[14 + off];
    const float* ln_g     = (const float*)d_in[15 + off];
    const float* ln_b     = (const float*)d_in[16 + off];
    float* out = (float*)d_out;

    init_kernel<<<(U_FLOAT4 + 255) / 256, 256>>>(time_b, wq, bq, att_bias);
    qnode_kernel<<<NUM_DST / 8, 128>>>(h, wq, bk);
    pq_kernel<<<dim3((NUM_DST + 63) / 64, (KDIM + 63) / 64), 256>>>(wk);
    scoreU_kernel<<<NUM_EDGES / 8, 256>>>(h, ef, dt, dst_idx, time_w, time_b);
    outfused_kernel<<<NUM_DST / 16, 256>>>(h, wv, bv, wout, bout, ln_g, ln_b, out);
}

// round 13
// speedup vs baseline: 1.0464x; 1.0328x over previous
#include <cuda_runtime.h>
#include <cuda_fp16.h>
#include <cstdint>

#define NUM_DST   10000
#define NUM_EDGES 600000
#define DN   100
#define DE   172
#define DTF  100
#define DOUT 128
#define KDIM (DN + DE + DTF)   // 372
#define NPC  6                 // k-pair chunks: k = it*64 + lane*2

// ---------------- scratch ----------------------------------------------------
__device__ float   g_qnodes[NUM_DST * DOUT];
__device__ float   g_qbk[NUM_DST * 2];
__device__ __half2 g_Pqh[(size_t)NUM_DST * KDIM];   // [d][k] -> (head0, head1) fp16
__device__ float2  g_U[(size_t)NUM_DST * KDIM];     // [d][k] -> (head0, head1) fp32
__device__ float   g_z[NUM_DST * 2];
__device__ float   g_qbias[DOUT];
__device__ float   g_absum[2];

#define U_FLOAT4 ((NUM_DST * KDIM * 2) / 4)   // 1,860,000
#define Z_FLOAT4 ((NUM_DST * 2) / 4)          // 5,000

__device__ __forceinline__ uint32_t to_tf32(float f) {
    uint32_t r;
    asm("cvt.rna.tf32.f32 %0, %1;" : "=r"(r) : "f"(f));
    return r;
}

// ---------------- kernel 0: init (vectorized zero) + derived constants -------
__global__ void init_kernel(const float* __restrict__ time_b,
                            const float* __restrict__ wq,
                            const float* __restrict__ bq,
                            const float* __restrict__ att_bias)
{
    int idx = blockIdx.x * blockDim.x + threadIdx.x;
    float4 zero4 = make_float4(0.f, 0.f, 0.f, 0.f);
    if (idx < U_FLOAT4) ((float4*)g_U)[idx] = zero4;
    if (idx < Z_FLOAT4) ((float4*)g_z)[idx] = zero4;
    if (idx < DOUT) {
        float acc = bq[idx];
        #pragma unroll 4
        for (int t = 0; t < DTF; t++)
            acc += cosf(time_b[t]) * wq[(DN + t) * DOUT + idx];
        g_qbias[idx] = acc;
    }
    if (idx < 2) {
        float s = 0.f;
        for (int j = 0; j < DOUT / 2; j++) s += att_bias[idx * (DOUT / 2) + j];
        g_absum[idx] = s;
    }
}

// ---------------- kernel 1: Q per dst node (8 dst / block) + Q.bk ------------
__global__ __launch_bounds__(128) void qnode_kernel(const float* __restrict__ h,
                                                    const float* __restrict__ wq,
                                                    const float* __restrict__ bk)
{
    int dbase = blockIdx.x * 8;
    int c = threadIdx.x;
    __shared__ float sh[8][DN];
    __shared__ float part[8][4];
    for (int i = c; i < 8 * DN; i += 128) {
        int dl = i / DN, k = i - dl * DN;
        sh[dl][k] = h[(size_t)(dbase + dl) * DN + k];
    }
    __syncthreads();
    float qb = g_qbias[c];
    float a[8];
    #pragma unroll
    for (int d = 0; d < 8; d++) a[d] = qb;
    #pragma unroll 4
    for (int k = 0; k < DN; k++) {
        float w = wq[k * DOUT + c];
        #pragma unroll
        for (int d = 0; d < 8; d++) a[d] = fmaf(sh[d][k], w, a[d]);
    }
    #pragma unroll
    for (int d = 0; d < 8; d++)
        g_qnodes[(dbase + d) * DOUT + c] = a[d];

    float bkc = bk[c];
    float p[8];
    #pragma unroll
    for (int d = 0; d < 8; d++) p[d] = a[d] * bkc;
    #pragma unroll
    for (int off = 16; off > 0; off >>= 1)
        #pragma unroll
        for (int d = 0; d < 8; d++)
            p[d] += __shfl_xor_sync(0xffffffffu, p[d], off);
    int warp = c >> 5;
    if ((c & 31) == 0)
        #pragma unroll
        for (int d = 0; d < 8; d++) part[d][warp] = p[d];
    __syncthreads();
    if (c < 16) {
        int d = c >> 1, hh = c & 1;
        g_qbk[(dbase + d) * 2 + hh] = part[d][hh * 2] + part[d][hh * 2 + 1];
    }
}

// ---------------- kernel 1b: Pq via tf32 MMA ---------------------------------
// Per head hh: Pq_hh[d, k] = sum_c qn[d, 64*hh+c] * wk[k, 64*hh+c]  (K=64).
// Block tile 128 dst x 128 k, 8 warps (wm 0..3 x wn 0..1, 32x64 each).
// A = As[d][c] row-major, B = Bs[c][n] (n = k-row of wk) -> mma.row.col.
__global__ __launch_bounds__(256) void pqmma_kernel(const float* __restrict__ wk)
{
    __shared__ float As[128][68];    // stride 68: conflict-free a-frags
    __shared__ float Bs[64][136];    // stride 136: conflict-free b-frags
    const int dbase = blockIdx.x * 128;
    const int kbase = blockIdx.y * 128;
    const int hh    = blockIdx.z;
    const int tid  = threadIdx.x;
    const int lane = tid & 31;
    const int wid  = tid >> 5;
    const int wm   = wid & 3;
    const int wn   = wid >> 2;

    for (int i = tid; i < 128 * 64; i += 256) {
        int r = i >> 6, c = i & 63;
        int d = dbase + r;
        float qv = (d < NUM_DST) ? g_qnodes[d * DOUT + hh * 64 + c] : 0.f;
        As[r][c] = __uint_as_float(to_tf32(qv));
    }
    for (int i = tid; i < 128 * 64; i += 256) {
        int n = i >> 6, c = i & 63;
        int k = kbase + n;
        float wv_ = (k < KDIM) ? wk[k * DOUT + hh * 64 + c] : 0.f;
        Bs[c][n] = __uint_as_float(to_tf32(wv_));
    }
    __syncthreads();

    float acc[2][8][4];
    #pragma unroll
    for (int mf = 0; mf < 2; mf++)
        #pragma unroll
        for (int nf = 0; nf < 8; nf++)
            #pragma unroll
            for (int r = 0; r < 4; r++) acc[mf][nf][r] = 0.f;

    #pragma unroll
    for (int ks = 0; ks < 8; ks++) {
        int acol = (lane & 3) + ks * 8;
        uint32_t a[2][4];
        #pragma unroll
        for (int mf = 0; mf < 2; mf++) {
            int rb = wm * 32 + mf * 16 + (lane >> 2);
            a[mf][0] = __float_as_uint(As[rb][acol]);
            a[mf][1] = __float_as_uint(As[rb + 8][acol]);
            a[mf][2] = __float_as_uint(As[rb][acol + 4]);
            a[mf][3] = __float_as_uint(As[rb + 8][acol + 4]);
        }
        int brow = (lane & 3) + ks * 8;
        #pragma unroll
        for (int nf = 0; nf < 8; nf++) {
            int bn = wn * 64 + nf * 8 + (lane >> 2);
            uint32_t b0 = __float_as_uint(Bs[brow][bn]);
            uint32_t b1 = __float_as_uint(Bs[brow + 4][bn]);
            #pragma unroll
            for (int mf = 0; mf < 2; mf++) {
                asm volatile(
                    "mma.sync.aligned.m16n8k8.row.col.f32.tf32.tf32.f32 "
                    "{%0,%1,%2,%3}, {%4,%5,%6,%7}, {%8,%9}, {%0,%1,%2,%3};"
                    : "+f"(acc[mf][nf][0]), "+f"(acc[mf][nf][1]),
                      "+f"(acc[mf][nf][2]), "+f"(acc[mf][nf][3])
                    : "r"(a[mf][0]), "r"(a[mf][1]), "r"(a[mf][2]), "r"(a[mf][3]),
                      "r"(b0), "r"(b1));
            }
        }
    }

    // epilogue: 16-bit element stores into the packed (h0,h1) half2 array
    __half* out16 = (__half*)g_Pqh;
    #pragma unroll
    for (int mf = 0; mf < 2; mf++) {
        #pragma unroll
        for (int rs = 0; rs < 2; rs++) {
            int d = dbase + wm * 32 + mf * 16 + rs * 8 + (lane >> 2);
            if (d >= NUM_DST) continue;
            #pragma unroll
            for (int nf = 0; nf < 8; nf++) {
                int k0 = kbase + wn * 64 + nf * 8 + 2 * (lane & 3);
                #pragma unroll
                for (int q = 0; q < 2; q++) {
                    int k = k0 + q;
                    if (k < KDIM)
                        out16[((size_t)d * KDIM + k) * 2 + hh] =
                            __float2half_rn(acc[mf][nf][rs * 2 + q]);
                }
            }
        }
    }
}

// ---------------- kernel 2: per-edge warp, k-pair mapping (UNCHANGED R12) ----
__global__ __launch_bounds__(256) void scoreU_kernel(
    const float* __restrict__ h,   const float* __restrict__ ef,
    const float* __restrict__ dt,  const int*   __restrict__ dst_idx,
    const float* __restrict__ time_w, const float* __restrict__ time_b)
{
    int e = (blockIdx.x * 256 + threadIdx.x) >> 5;
    if (e >= NUM_EDGES) return;
    int lane = threadIdx.x & 31;
    float td = dt[e];
    int d = dst_idx[e];
    const float* __restrict__ hrow  = h + (size_t)(NUM_DST + e) * DN;
    const float* __restrict__ efrow = ef + (size_t)e * DE;
    const int k2 = lane * 2;

    float2 v[NPC];
    #pragma unroll
    for (int it = 0; it < 5; it++) {
        int k = it * 64 + k2;
        float2 t;
        if (k < DN) {
            t = __ldcs((const float2*)(hrow + k));
        } else if (k < DN + DE) {
            t = __ldcs((const float2*)(efrow + (k - DN)));
        } else {
            int t0 = k - DN - DE;
            t.x = __cosf(td * time_w[t0]     + time_b[t0]);
            t.y = __cosf(td * time_w[t0 + 1] + time_b[t0 + 1]);
        }
        v[it] = t;
    }
    {
        int k = 5 * 64 + k2;
        float2 t = make_float2(0.f, 0.f);
        if (k < KDIM) {
            int t0 = k - DN - DE;
            t.x = __cosf(td * time_w[t0]     + time_b[t0]);
            t.y = __cosf(td * time_w[t0 + 1] + time_b[t0 + 1]);
        }
        v[5] = t;
    }

    const __half2* __restrict__ pq = g_Pqh + (size_t)d * KDIM;
    float2 p[NPC][2];
    #pragma unroll
    for (int it = 0; it < 5; it++) {
        uint2 raw = __ldg((const uint2*)(pq + it * 64 + k2));
        p[it][0] = __half22float2(*(__half2*)&raw.x);
        p[it][1] = __half22float2(*(__half2*)&raw.y);
    }
    if (5 * 64 + k2 < KDIM) {
        uint2 raw = __ldg((const uint2*)(pq + 5 * 64 + k2));
        p[5][0] = __half22float2(*(__half2*)&raw.x);
        p[5][1] = __half22float2(*(__half2*)&raw.y);
    } else {
        p[5][0] = make_float2(0.f, 0.f);
        p[5][1] = make_float2(0.f, 0.f);
    }

    float a0 = 0.f, a1 = 0.f;
    #pragma unroll
    for (int it = 0; it < NPC; it++) {
        a0 = fmaf(v[it].x, p[it][0].x, a0);
        a1 = fmaf(v[it].x, p[it][0].y, a1);
        a0 = fmaf(v[it].y, p[it][1].x, a0);
        a1 = fmaf(v[it].y, p[it][1].y, a1);
    }
    #pragma unroll
    for (int off = 16; off > 0; off >>= 1) {
        a0 += __shfl_xor_sync(0xffffffffu, a0, off);
        a1 += __shfl_xor_sync(0xffffffffu, a1, off);
    }
    float2 qbk = *(const float2*)(g_qbk + d * 2);
    float s0 = a0 + g_absum[0] + qbk.x;
    float s1 = a1 + g_absum[1] + qbk.y;
    s0 = s0 > 0.f ? s0 : 0.2f * s0;
    s1 = s1 > 0.f ? s1 : 0.2f * s1;
    float e0 = __expf(fminf(s0, 80.f));
    float e1 = __expf(fminf(s1, 80.f));
    if (lane == 0) {
        asm volatile("red.global.add.v2.f32 [%0], {%1,%2};"
                     :: "l"(g_z + d * 2), "f"(e0), "f"(e1) : "memory");
    }
    float2* __restrict__ Urow = g_U + (size_t)d * KDIM;
    #pragma unroll
    for (int it = 0; it < 5; it++) {
        int k = it * 64 + k2;
        float x0 = v[it].x * e0;
        float y0 = v[it].x * e1;
        float x1 = v[it].y * e0;
        float y1 = v[it].y * e1;
        asm volatile("red.global.add.v4.f32 [%0], {%1,%2,%3,%4};"
                     :: "l"(Urow + k), "f"(x0), "f"(y0), "f"(x1), "f"(y1)
                     : "memory");
    }
    if (5 * 64 + k2 < KDIM) {
        float x0 = v[5].x * e0;
        float y0 = v[5].x * e1;
        float x1 = v[5].y * e0;
        float y1 = v[5].y * e1;
        asm volatile("red.global.add.v4.f32 [%0], {%1,%2,%3,%4};"
                     :: "l"(Urow + 5 * 64 + k2), "f"(x0), "f"(y0), "f"(x1), "f"(y1)
                     : "memory");
    }
}

// ---------------- kernel 3: fused agg+out+LN, 16 dst / 256-thread block ------
__global__ __launch_bounds__(256) void outfused_kernel(
    const float* __restrict__ h,    const float* __restrict__ wv,
    const float* __restrict__ bv,   const float* __restrict__ wout,
    const float* __restrict__ bout, const float* __restrict__ ln_g,
    const float* __restrict__ ln_b, float* __restrict__ out)
{
    int dbase = blockIdx.x * 16;
    int t = threadIdx.x;
    int c = t & 127;
    int g = t >> 7;
    int hh = c >> 6;
    __shared__ float sU[16][KDIM * 2];
    __shared__ float sZ[16][2];
    __shared__ float sin[16][DOUT + DN];
    __shared__ float red1[16][4], red2[16][4];

    if (t < 32) {
        int d = t >> 1, j = t & 1;
        sZ[d][j] = g_z[(dbase + d) * 2 + j];
    }
    __syncthreads();
    for (int i = t; i < 16 * KDIM * 2; i += 256) {
        int d = i / (KDIM * 2);
        int j = i - d * (KDIM * 2);
        float z = sZ[d][j & 1];
        float u = ((const float*)(g_U + (size_t)(dbase + d) * KDIM))[j];
        sU[d][j] = (z > 0.f) ? (u / z) : 0.f;
    }
    for (int i = t; i < 16 * DN; i += 256) {
        int d = i / DN, k = i - d * DN;
        sin[d][DOUT + k] = h[(size_t)(dbase + d) * DN + k];
    }
    __syncthreads();

    float acc[8];
    #pragma unroll
    for (int d = 0; d < 8; d++) acc[d] = 0.f;
    #pragma unroll 4
    for (int k = 0; k < KDIM; k++) {
        float w = wv[k * DOUT + c];
        #pragma unroll
        for (int d = 0; d < 8; d++)
            acc[d] = fmaf(sU[g * 8 + d][k * 2 + hh], w, acc[d]);
    }
    float bvc = bv[c];
    #pragma unroll
    for (int d = 0; d < 8; d++)
        sin[g * 8 + d][c] = (sZ[g * 8 + d][hh] > 0.f) ? (acc[d] + bvc) : 0.f;
    __syncthreads();

    float b0 = bout[c];
    float a[8];
    #pragma unroll
    for (int d = 0; d < 8; d++) a[d] = b0;
    #pragma unroll 4
    for (int k = 0; k < DOUT + DN; k++) {
        float w = wout[k * DOUT + c];
        #pragma unroll
        for (int d = 0; d < 8; d++) a[d] = fmaf(sin[g * 8 + d][k], w, a[d]);
    }
    float s1[8], s2[8];
    #pragma unroll
    for (int d = 0; d < 8; d++) {
        a[d] = fmaxf(a[d], 0.f);
        s1[d] = a[d];
        s2[d] = a[d] * a[d];
    }
    #pragma unroll
    for (int off = 16; off > 0; off >>= 1) {
        #pragma unroll
        for (int d = 0; d < 8; d++) {
            s1[d] += __shfl_xor_sync(0xffffffffu, s1[d], off);
            s2[d] += __shfl_xor_sync(0xffffffffu, s2[d], off);
        }
    }
    int warp = (t >> 5) & 3;
    if ((t & 31) == 0) {
        #pragma unroll
        for (int d = 0; d < 8; d++) {
            red1[g * 8 + d][warp] = s1[d];
            red2[g * 8 + d][warp] = s2[d];
        }
    }
    __syncthreads();
    #pragma unroll
    for (int d = 0; d < 8; d++) {
        int dd = g * 8 + d;
        float t1 = red1[dd][0] + red1[dd][1] + red1[dd][2] + red1[dd][3];
        float t2 = red2[dd][0] + red2[dd][1] + red2[dd][2] + red2[dd][3];
        float mu  = t1 * (1.f / DOUT);
        float var = t2 * (1.f / DOUT) - mu * mu;
        out[(size_t)(dbase + dd) * DOUT + c] =
            (a[d] - mu) * rsqrtf(var + 1e-5f) * ln_g[c] + ln_b[c];
    }
}

// ---------------- launch -----------------------------------------------------
extern "C" void kernel_launch(void* const* d_in, const int* in_sizes, int n_in,
                              void* d_out, int out_size)
{
    int off = (n_in >= 18 && in_sizes[4] == 1) ? 1 : 0;
    const float* h        = (const float*)d_in[0];
    const float* ef       = (const float*)d_in[1];
    const float* dt       = (const float*)d_in[2];
    const int*   dst_idx  = (const int*)  d_in[3];
    const float* time_w   = (const float*)d_in[4 + off];
    const float* time_b   = (const float*)d_in[5 + off];
    const float* wq       = (const float*)d_in[6 + off];
    const float* bq       = (const float*)d_in[7 + off];
    const float* wk       = (const float*)d_in[8 + off];
    const float* bk       = (const float*)d_in[9 + off];
    const float* wv       = (const float*)d_in[10 + off];
    const float* bv       = (const float*)d_in[11 + off];
    const float* att_bias = (const float*)d_in[12 + off];
    const float* wout     = (const float*)d_in[13 + off];
    const float* bout     = (const float*)d_in[14 + off];
    const float* ln_g     = (const float*)d_in[15 + off];
    const float* ln_b     = (const float*)d_in[16 + off];
    float* out = (float*)d_out;

    init_kernel<<<(U_FLOAT4 + 255) / 256, 256>>>(time_b, wq, bq, att_bias);
    qnode_kernel<<<NUM_DST / 8, 128>>>(h, wq, bk);
    pqmma_kernel<<<dim3((NUM_DST + 127) / 128, (KDIM + 127) / 128, 2), 256>>>(wk);
    scoreU_kernel<<<NUM_EDGES / 8, 256>>>(h, ef, dt, dst_idx, time_w, time_b);
    outfused_kernel<<<NUM_DST / 16, 256>>>(h, wv, bv, wout, bout, ln_g, ln_b, out);
}